// round 8
// baseline (speedup 1.0000x reference)
#include <cuda_runtime.h>
#include <math.h>

typedef unsigned long long u64;

#define FMA2(d, a, b, c) \
    asm("fma.rn.f32x2 %0, %1, %2, %3;" : "=l"(d) : "l"(a), "l"(b), "l"(c))
#define PACK2(d, lo, hi) \
    asm("mov.b64 %0, {%1, %2};" : "=l"(d) : "f"(lo), "f"(hi))
#define UNPACK2(lo, hi, d) \
    asm("mov.b64 {%0, %1}, %2;" : "=f"(lo), "=f"(hi) : "l"(d))
#define LDS_V2B64(a, b, addr) \
    asm volatile("ld.shared.v2.b64 {%0, %1}, [%2];" : "=l"(a), "=l"(b) : "r"(addr))

#define N_IN   4096
#define N_OUT  1024
#define BATCH  16
#define E_MAX  81920
#define VB_STRIDE (32 * E_MAX)

__device__ float g_featT2[N_IN * 512];                 // [n][c*16+b]
__device__ float g_Vbuf[(size_t)BATCH * VB_STRIDE];
__device__ float g_h2T[64 * E_MAX];                    // [c][e]
__device__ int   g_is64;
__device__ int   g_seg[E_MAX];
__device__ int   g_src[E_MAX];

// ---------------- phase -1: dtype detect + index normalize ------------------
__global__ void detect_idx(const int* __restrict__ idx32, int E) {
    __shared__ int any;
    if (threadIdx.x == 0) any = 0;
    __syncthreads();
    int n = min(E, 512);
    int local = 0;
    for (int m = threadIdx.x; m < n; m += 256)
        local |= idx32[4 * m + 1] | idx32[4 * m + 3];
    if (local) atomicOr(&any, 1);
    __syncthreads();
    if (threadIdx.x == 0) g_is64 = any ? 0 : 1;
}

__global__ void convert_idx(const int* __restrict__ idx32, int E) {
    int m = blockIdx.x * 256 + threadIdx.x;
    if (m >= E) return;
    if (g_is64) { g_seg[m] = idx32[4 * m];     g_src[m] = idx32[4 * m + 2]; }
    else        { g_seg[m] = idx32[2 * m];     g_src[m] = idx32[2 * m + 1]; }
}

// ---------------- phase 0: tiled permute feat[b][c][n] -> featT2[n][c*16+b]
__global__ void prep_featT(const float* __restrict__ feat) {
    __shared__ float tile[32][33];
    int n0  = blockIdx.x * 32;
    int cb0 = blockIdx.y * 32;
    int tx = threadIdx.x, ty = threadIdx.y;       // 32 x 8
    #pragma unroll
    for (int i = ty; i < 32; i += 8) {
        int cb = cb0 + i;
        int row = (cb & 15) * 32 + (cb >> 4);     // b*32 + c
        tile[i][tx] = feat[(size_t)row * N_IN + n0 + tx];
    }
    __syncthreads();
    #pragma unroll
    for (int i = ty; i < 32; i += 8)
        g_featT2[(size_t)(n0 + i) * 512 + cb0 + tx] = tile[tx][i];
}

// ---------------- phase 0b: h2 for all edges -> g_h2T[c][e] ------------------
// 256 threads, 64 edges/block. thread owns (e = t&63, cols cg*16..cg*16+15)
__global__ __launch_bounds__(256) void prep_h2(
    const float* __restrict__ W1, const float* __restrict__ W2,
    const float* __restrict__ eval_locs, int E)
{
    __shared__ float locs[128];
    __shared__ float h1t[64 * 65];     // [j][e] pad 65
    __shared__ float W2s[64 * 64];
    const int t  = threadIdx.x;
    const int e0 = blockIdx.x * 64;

    #pragma unroll
    for (int r = 0; r < 16; r++)
        W2s[t + 256 * r] = W2[t + 256 * r];

    if (t < 128) {
        int idx = 2 * e0 + t;
        locs[t] = (idx < 2 * E) ? eval_locs[idx] : 0.f;
    }
    __syncthreads();

    // h1t[j][e] = sin(loc_e . W1[:,j])
    #pragma unroll
    for (int r = 0; r < 16; r++) {
        int id = t + 256 * r;
        int j = id & 63;
        int e = id >> 6;
        h1t[j * 65 + e] = __sinf(locs[2 * e] * W1[j] + locs[2 * e + 1] * W1[64 + j]);
    }
    __syncthreads();

    const int e  = t & 63;
    const int cg = t >> 6;             // 4 col groups of 16
    const unsigned w2b = (unsigned)__cvta_generic_to_shared(W2s);
    u64 acc[8];
    #pragma unroll
    for (int i = 0; i < 8; i++) acc[i] = 0ull;

    #pragma unroll 8
    for (int k = 0; k < 64; k++) {
        float hv = h1t[k * 65 + e];
        u64 hh; PACK2(hh, hv, hv);
        const unsigned wa = w2b + (k * 64 + cg * 16) * 4;
        u64 w0, w1, w2v, w3v, w4, w5, w6, w7;
        LDS_V2B64(w0, w1, wa);
        LDS_V2B64(w2v, w3v, wa + 16);
        LDS_V2B64(w4, w5, wa + 32);
        LDS_V2B64(w6, w7, wa + 48);
        FMA2(acc[0], hh, w0, acc[0]);
        FMA2(acc[1], hh, w1, acc[1]);
        FMA2(acc[2], hh, w2v, acc[2]);
        FMA2(acc[3], hh, w3v, acc[3]);
        FMA2(acc[4], hh, w4, acc[4]);
        FMA2(acc[5], hh, w5, acc[5]);
        FMA2(acc[6], hh, w6, acc[6]);
        FMA2(acc[7], hh, w7, acc[7]);
    }

    #pragma unroll
    for (int i = 0; i < 8; i++) {
        float lo, hi;
        UNPACK2(lo, hi, acc[i]);
        g_h2T[(size_t)(cg * 16 + 2 * i)     * E_MAX + e0 + e] = __sinf(lo);
        g_h2T[(size_t)(cg * 16 + 2 * i + 1) * E_MAX + e0 + e] = __sinf(hi);
    }
}

// ---------------- phase A -----------------------------------------------
// 256 threads, 16 edges/block, 2 blocks/SM. smem (floats):
//  h2t[64][20]     @0      (1280)   h2t[k][e]
//  g  [8][16][36]  @1280   (4608)
//  filt[8][32][36] @5888   (9216)
//  goff[512] int   @15104
#define OFF_H2T  0
#define OFF_G    1280
#define OFF_F    5888
#define OFF_GOFF 15104
#define SMEM_A_FLOATS 15616
#define SMEM_A_BYTES  (SMEM_A_FLOATS * 4)

__global__ __launch_bounds__(256, 2) void quad_main(
    const float* __restrict__ W3, int E)
{
    extern __shared__ float sm[];
    float* h2t = sm + OFF_H2T;
    float* g_s = sm + OFF_G;
    float* f_s = sm + OFF_F;
    int*   goff = (int*)(sm + OFF_GOFF);
    const unsigned smb = (unsigned)__cvta_generic_to_shared(sm);

    const int t   = threadIdx.x;
    const int e0  = blockIdx.x * 16;
    const int net = min(16, E - e0);

    // gather offsets per (e, ci): m = (e0+e)*32+ci ; channel c = m/E, row m%E
    #pragma unroll
    for (int r = 0; r < 2; r++) {
        int p = t + 256 * r;              // 0..511
        int e = p >> 5;
        if (e < net) {
            int m  = (e0 + e) * 32 + (p & 31);
            int c  = m / E;
            int rr = m - c * E;
            goff[p] = g_src[rr] * 512 + c * 16;
        }
    }

    // load h2t[k][e] from g_h2T (always in-bounds; padded edges deterministic)
    #pragma unroll
    for (int r = 0; r < 4; r++) {
        int i = t + 256 * r;              // 0..1023
        int k = i >> 4, e = i & 15;
        h2t[k * 20 + e] = g_h2T[(size_t)k * E_MAX + e0 + e];
    }
    __syncthreads();

    // ---- filter gen (f32x2): thread owns 4 cols {4t..4t+3}, all 16 edges.
    u64 acc[4][8];
    #pragma unroll
    for (int c = 0; c < 4; c++)
        #pragma unroll
        for (int p = 0; p < 8; p++) acc[c][p] = 0ull;

    const float4* w3p4 = (const float4*)W3 + t;     // row stride 256 float4
    float4 wcur = w3p4[0];

    #pragma unroll 8
    for (int k = 0; k < 64; k++) {
        float4 wnext = (k < 63) ? w3p4[(k + 1) * 256] : wcur;
        u64 wa, wb, wc, wd;
        PACK2(wa, wcur.x, wcur.x);
        PACK2(wb, wcur.y, wcur.y);
        PACK2(wc, wcur.z, wcur.z);
        PACK2(wd, wcur.w, wcur.w);
        const unsigned ha = smb + (OFF_H2T + k * 20) * 4;
        u64 hp[8];
        LDS_V2B64(hp[0], hp[1], ha);
        LDS_V2B64(hp[2], hp[3], ha + 16);
        LDS_V2B64(hp[4], hp[5], ha + 32);
        LDS_V2B64(hp[6], hp[7], ha + 48);
        #pragma unroll
        for (int p = 0; p < 8; p++) {
            FMA2(acc[0][p], wa, hp[p], acc[0][p]);
            FMA2(acc[1][p], wb, hp[p], acc[1][p]);
            FMA2(acc[2][p], wc, hp[p], acc[2][p]);
            FMA2(acc[3][p], wd, hp[p], acc[3][p]);
        }
        wcur = wnext;
    }

    // mappings
    const int fci = t >> 3;              // filt store: col 4t -> ci
    const int fco = (t & 7) * 4;
    const int ea  = t >> 5;              // apply: edge within sub (0..7)
    const int b0  = ((t >> 2) & 7) * 2;  //        2 batches
    const int j0  = (t & 3) * 8;         //        8 consecutive co

    #pragma unroll
    for (int sub = 0; sub < 2; sub++) {
        const int es0 = sub * 8;

        // staged gather of 8 edges: g[e][b][ci]
        #pragma unroll
        for (int r = 0; r < 16; r++) {
            int i  = t + 256 * r;             // 0..4095
            int p8 = i >> 4;                  // (e,ci) 0..255
            int b  = i & 15;
            int e  = p8 >> 5, ci = p8 & 31;
            float v = (es0 + e < net) ? g_featT2[goff[(es0 + e) * 32 + ci] + b] : 0.f;
            g_s[e * 576 + b * 36 + ci] = v;
        }
        // store this sub's filters: edge pairs 4*sub..4*sub+3
        #pragma unroll
        for (int p = 0; p < 4; p++) {
            int pp = sub * 4 + p;
            float x0, x1, y0, y1, z0, z1, w0, w1;
            UNPACK2(x0, x1, acc[0][pp]);
            UNPACK2(y0, y1, acc[1][pp]);
            UNPACK2(z0, z1, acc[2][pp]);
            UNPACK2(w0, w1, acc[3][pp]);
            *(float4*)&f_s[(2 * p)     * 1152 + fci * 36 + fco] = make_float4(x0, y0, z0, w0);
            *(float4*)&f_s[(2 * p + 1) * 1152 + fci * 36 + fco] = make_float4(x1, y1, z1, w1);
        }
        __syncthreads();

        // apply (f32x2): 2 batches x 8 co per thread, one edge
        if (es0 + ea < net) {
            const float* gp0 = &g_s[ea * 576 + b0 * 36];
            const float* gp1 = gp0 + 36;
            const unsigned fpa = smb + (OFF_F + ea * 1152 + j0) * 4;
            u64 a0[4] = {0ull, 0ull, 0ull, 0ull};
            u64 a1[4] = {0ull, 0ull, 0ull, 0ull};
            #pragma unroll
            for (int ci4 = 0; ci4 < 32; ci4 += 4) {
                float4 gv0 = *(const float4*)&gp0[ci4];
                float4 gv1 = *(const float4*)&gp1[ci4];
                float g0v[4] = {gv0.x, gv0.y, gv0.z, gv0.w};
                float g1v[4] = {gv1.x, gv1.y, gv1.z, gv1.w};
                #pragma unroll
                for (int kk = 0; kk < 4; kk++) {
                    u64 f01, f23, f45, f67;
                    LDS_V2B64(f01, f23, fpa + (ci4 + kk) * 144);
                    LDS_V2B64(f45, f67, fpa + (ci4 + kk) * 144 + 16);
                    u64 d0; PACK2(d0, g0v[kk], g0v[kk]);
                    FMA2(a0[0], d0, f01, a0[0]);
                    FMA2(a0[1], d0, f23, a0[1]);
                    FMA2(a0[2], d0, f45, a0[2]);
                    FMA2(a0[3], d0, f67, a0[3]);
                    u64 d1; PACK2(d1, g1v[kk], g1v[kk]);
                    FMA2(a1[0], d1, f01, a1[0]);
                    FMA2(a1[1], d1, f23, a1[1]);
                    FMA2(a1[2], d1, f45, a1[2]);
                    FMA2(a1[3], d1, f67, a1[3]);
                }
            }
            size_t m = (size_t)(e0 + es0 + ea) * 32 + j0;
            float* vb0 = &g_Vbuf[(size_t)b0 * VB_STRIDE + m];
            float* vb1 = vb0 + VB_STRIDE;
            ulonglong2 s0a; s0a.x = a0[0]; s0a.y = a0[1];
            ulonglong2 s0b; s0b.x = a0[2]; s0b.y = a0[3];
            ulonglong2 s1a; s1a.x = a1[0]; s1a.y = a1[1];
            ulonglong2 s1b; s1b.x = a1[2]; s1b.y = a1[3];
            *(ulonglong2*)vb0       = s0a;
            *(ulonglong2*)(vb0 + 4) = s0b;
            *(ulonglong2*)vb1       = s1a;
            *(ulonglong2*)(vb1 + 4) = s1b;
        }
        __syncthreads();
    }
}

// ---------------- phase B: out[b][c][o] = sum over seg-range of Vbuf[b][c*E + r]
__global__ __launch_bounds__(512) void quad_scatter(float* __restrict__ out, int E)
{
    const int o  = blockIdx.x;
    const int c0 = blockIdx.y * 8;
    int lo = 0, hi = E;
    while (lo < hi) { int m = (lo + hi) >> 1; if (g_seg[m] <  o) lo = m + 1; else hi = m; }
    const int r0 = lo;
    hi = E;
    while (lo < hi) { int m = (lo + hi) >> 1; if (g_seg[m] <= o) lo = m + 1; else hi = m; }
    const int r1 = lo;

    const int b = threadIdx.x >> 5;     // warp = batch
    const int l = threadIdx.x & 31;

    #pragma unroll
    for (int cc = 0; cc < 8; cc++) {
        int c = c0 + cc;
        const float* p = &g_Vbuf[(size_t)b * VB_STRIDE + (size_t)c * E];
        float s = 0.f;
        for (int r = r0 + l; r < r1; r += 32) s += p[r];
        #pragma unroll
        for (int d = 16; d; d >>= 1) s += __shfl_xor_sync(0xffffffffu, s, d);
        if (l == 0) out[b * 32768 + c * 1024 + o] = s;
    }
}

extern "C" void kernel_launch(void* const* d_in, const int* in_sizes, int n_in,
                              void* d_out, int out_size) {
    const float* features  = (const float*)d_in[0];
    const float* W1        = (const float*)d_in[1];
    const float* W2        = (const float*)d_in[2];
    const float* W3        = (const float*)d_in[3];
    const float* eval_locs = (const float*)d_in[4];
    const int*   eval_idx  = (const int*)d_in[5];
    float*       out       = (float*)d_out;

    const int E = in_sizes[4] / 2;

    cudaFuncSetAttribute(quad_main, cudaFuncAttributeMaxDynamicSharedMemorySize,
                         SMEM_A_BYTES);

    detect_idx<<<1, 256>>>(eval_idx, E);
    convert_idx<<<(E + 255) / 256, 256>>>(eval_idx, E);
    prep_featT<<<dim3(N_IN / 32, 512 / 32), dim3(32, 8)>>>(features);
    prep_h2<<<(E + 63) / 64, 256>>>(W1, W2, eval_locs, E);
    quad_main<<<(E + 15) / 16, 256, SMEM_A_BYTES>>>(W3, E);
    quad_scatter<<<dim3(N_OUT, 4), 512>>>(out, E);
}

// round 10
// speedup vs baseline: 1.0693x; 1.0693x over previous
#include <cuda_runtime.h>
#include <math.h>

typedef unsigned long long u64;

#define FMA2(d, a, b, c) \
    asm("fma.rn.f32x2 %0, %1, %2, %3;" : "=l"(d) : "l"(a), "l"(b), "l"(c))
#define PACK2(d, lo, hi) \
    asm("mov.b64 %0, {%1, %2};" : "=l"(d) : "f"(lo), "f"(hi))
#define UNPACK2(lo, hi, d) \
    asm("mov.b64 {%0, %1}, %2;" : "=f"(lo), "=f"(hi) : "l"(d))
#define LDS_V2B64(a, b, addr) \
    asm volatile("ld.shared.v2.b64 {%0, %1}, [%2];" : "=l"(a), "=l"(b) : "r"(addr))

#define N_IN   4096
#define N_OUT  1024
#define BATCH  16
#define E_MAX  81920
#define VB_STRIDE (32 * E_MAX)

__device__ float g_featT2[N_IN * 512];                 // [n][c*16+b]
__device__ float g_Vbuf[(size_t)BATCH * VB_STRIDE];
__device__ int   g_is64;
__device__ int   g_seg[E_MAX];
__device__ int   g_src[E_MAX];
__device__ int   g_bnd[N_OUT + 1];

// ---------------- phase -1: dtype detect + index normalize ------------------
__global__ void detect_idx(const int* __restrict__ idx32, int E) {
    __shared__ int any;
    if (threadIdx.x == 0) any = 0;
    __syncthreads();
    int n = min(E, 512);
    int local = 0;
    for (int m = threadIdx.x; m < n; m += 256)
        local |= idx32[4 * m + 1] | idx32[4 * m + 3];
    if (local) atomicOr(&any, 1);
    __syncthreads();
    if (threadIdx.x == 0) g_is64 = any ? 0 : 1;
}

__global__ void convert_idx(const int* __restrict__ idx32, int E) {
    int m = blockIdx.x * 256 + threadIdx.x;
    if (m >= E) return;
    if (g_is64) { g_seg[m] = idx32[4 * m];     g_src[m] = idx32[4 * m + 2]; }
    else        { g_seg[m] = idx32[2 * m];     g_src[m] = idx32[2 * m + 1]; }
}

// ---------------- phase -0.5: segment boundaries (seg sorted) ---------------
__global__ void seg_bounds(int E) {
    int o = blockIdx.x * 256 + threadIdx.x;
    if (o > N_OUT) return;
    int lo = 0, hi = E;
    while (lo < hi) { int m = (lo + hi) >> 1; if (g_seg[m] < o) lo = m + 1; else hi = m; }
    g_bnd[o] = lo;
}

// ---------------- phase 0: tiled permute feat[b][c][n] -> featT2[n][c*16+b]
__global__ void prep_featT(const float* __restrict__ feat) {
    __shared__ float tile[32][33];
    int n0  = blockIdx.x * 32;
    int cb0 = blockIdx.y * 32;
    int tx = threadIdx.x, ty = threadIdx.y;       // 32 x 8
    #pragma unroll
    for (int i = ty; i < 32; i += 8) {
        int cb = cb0 + i;
        int row = (cb & 15) * 32 + (cb >> 4);     // b*32 + c
        tile[i][tx] = feat[(size_t)row * N_IN + n0 + tx];
    }
    __syncthreads();
    #pragma unroll
    for (int i = ty; i < 32; i += 8)
        g_featT2[(size_t)(n0 + i) * 512 + cb0 + tx] = tile[tx][i];
}

// ---------------- phase A (verified R7 version) ---------------------------
// 256 threads, 16 edges/block, 2 blocks/SM. smem (floats):
//  h1 [16][64]     @0      (1024)
//  h2t[64][20]     @1024   (1280)   transposed: h2t[k][e], pad 20
//  W2s[64][64]     @2304   (4096)
//  g  [8][16][36]  @6400   (4608)
//  filt[8][32][36] @11008  (9216)
//  locs[32]        @20224
//  goff[512] int   @20256
#define OFF_H1   0
#define OFF_H2T  1024
#define OFF_W2S  2304
#define OFF_G    6400
#define OFF_F    11008
#define OFF_LOCS 20224
#define OFF_GOFF 20256
#define SMEM_A_FLOATS 20768
#define SMEM_A_BYTES  (SMEM_A_FLOATS * 4)

__global__ __launch_bounds__(256, 2) void quad_main(
    const float* __restrict__ W1, const float* __restrict__ W2,
    const float* __restrict__ W3, const float* __restrict__ eval_locs, int E)
{
    extern __shared__ float sm[];
    float* h1_s = sm + OFF_H1;
    float* h2t  = sm + OFF_H2T;
    float* W2s  = sm + OFF_W2S;
    float* g_s  = sm + OFF_G;
    float* f_s  = sm + OFF_F;
    float* locs = sm + OFF_LOCS;
    int*   goff = (int*)(sm + OFF_GOFF);
    const unsigned smb = (unsigned)__cvta_generic_to_shared(sm);

    const int t   = threadIdx.x;
    const int e0  = blockIdx.x * 16;
    const int net = min(16, E - e0);

    if (t < 2 * net) locs[t] = eval_locs[2 * e0 + t];

    // stage W2 into smem (coalesced, once per block)
    #pragma unroll
    for (int r = 0; r < 16; r++)
        W2s[t + 256 * r] = W2[t + 256 * r];

    // gather offsets per (e, ci): m = (e0+e)*32+ci ; channel c = m/E, row m%E
    #pragma unroll
    for (int r = 0; r < 2; r++) {
        int p = t + 256 * r;              // 0..511
        int e = p >> 5;
        if (e < net) {
            int m  = (e0 + e) * 32 + (p & 31);
            int c  = m / E;
            int rr = m - c * E;
            goff[p] = g_src[rr] * 512 + c * 16;
        }
    }
    __syncthreads();

    // h1[e][j] = sin(loc_e . W1[:,j])   (0 for padded edges)
    #pragma unroll
    for (int r = 0; r < 4; r++) {
        int id = t + 256 * r;             // 0..1023
        int e = id >> 6, j = id & 63;
        float v = 0.f;
        if (e < net)
            v = __sinf(locs[2 * e] * W1[j] + locs[2 * e + 1] * W1[64 + j]);
        h1_s[id] = v;
    }
    __syncthreads();

    // ---- h2 (f32x2): thread owns (e = t>>4, cols j0..j0+3); writes h2t[j][e]
    {
        const int e  = t >> 4;
        const int j0 = (t & 15) * 4;
        u64 aA = 0ull, aB = 0ull;
        #pragma unroll
        for (int k4 = 0; k4 < 64; k4 += 4) {
            float4 hv = *(const float4*)&h1_s[e * 64 + k4];
            float hs[4] = {hv.x, hv.y, hv.z, hv.w};
            #pragma unroll
            for (int kk = 0; kk < 4; kk++) {
                u64 hh; PACK2(hh, hs[kk], hs[kk]);
                u64 w01, w23;
                LDS_V2B64(w01, w23, smb + (OFF_W2S + (k4 + kk) * 64 + j0) * 4);
                FMA2(aA, hh, w01, aA);
                FMA2(aB, hh, w23, aB);
            }
        }
        float s0, s1, s2, s3;
        UNPACK2(s0, s1, aA);
        UNPACK2(s2, s3, aB);
        s0 = __sinf(s0); s1 = __sinf(s1); s2 = __sinf(s2); s3 = __sinf(s3);
        if (e >= net) { s0 = s1 = s2 = s3 = 0.f; }
        h2t[(j0 + 0) * 20 + e] = s0;
        h2t[(j0 + 1) * 20 + e] = s1;
        h2t[(j0 + 2) * 20 + e] = s2;
        h2t[(j0 + 3) * 20 + e] = s3;
    }
    __syncthreads();

    // ---- filter gen (f32x2): thread owns 4 cols {4t..4t+3}, all 16 edges.
    // acc[c][p]: c = col 0..3, p = edge pair 0..7
    u64 acc[4][8];
    #pragma unroll
    for (int c = 0; c < 4; c++)
        #pragma unroll
        for (int p = 0; p < 8; p++) acc[c][p] = 0ull;

    const float4* w3p4 = (const float4*)W3 + t;     // row stride 256 float4
    float4 wcur = w3p4[0];

    #pragma unroll 8
    for (int k = 0; k < 64; k++) {
        float4 wnext = (k < 63) ? w3p4[(k + 1) * 256] : wcur;
        u64 wa, wb, wc, wd;
        PACK2(wa, wcur.x, wcur.x);
        PACK2(wb, wcur.y, wcur.y);
        PACK2(wc, wcur.z, wcur.z);
        PACK2(wd, wcur.w, wcur.w);
        const unsigned ha = smb + (OFF_H2T + k * 20) * 4;
        u64 hp[8];
        LDS_V2B64(hp[0], hp[1], ha);
        LDS_V2B64(hp[2], hp[3], ha + 16);
        LDS_V2B64(hp[4], hp[5], ha + 32);
        LDS_V2B64(hp[6], hp[7], ha + 48);
        #pragma unroll
        for (int p = 0; p < 8; p++) {
            FMA2(acc[0][p], wa, hp[p], acc[0][p]);
            FMA2(acc[1][p], wb, hp[p], acc[1][p]);
            FMA2(acc[2][p], wc, hp[p], acc[2][p]);
            FMA2(acc[3][p], wd, hp[p], acc[3][p]);
        }
        wcur = wnext;
    }

    // mappings
    const int fci = t >> 3;              // filt store: col 4t -> ci
    const int fco = (t & 7) * 4;
    const int ea  = t >> 5;              // apply: edge within sub (0..7)
    const int b0  = ((t >> 2) & 7) * 2;  //        2 batches
    const int j0  = (t & 3) * 8;         //        8 consecutive co

    #pragma unroll
    for (int sub = 0; sub < 2; sub++) {
        const int es0 = sub * 8;

        // staged gather of 8 edges: g[e][b][ci]
        #pragma unroll
        for (int r = 0; r < 16; r++) {
            int i  = t + 256 * r;             // 0..4095
            int p8 = i >> 4;                  // (e,ci) 0..255
            int b  = i & 15;
            int e  = p8 >> 5, ci = p8 & 31;
            float v = (es0 + e < net) ? g_featT2[goff[(es0 + e) * 32 + ci] + b] : 0.f;
            g_s[e * 576 + b * 36 + ci] = v;
        }
        // store this sub's filters: edge pairs 4*sub..4*sub+3
        #pragma unroll
        for (int p = 0; p < 4; p++) {
            int pp = sub * 4 + p;
            float x0, x1, y0, y1, z0, z1, w0, w1;
            UNPACK2(x0, x1, acc[0][pp]);
            UNPACK2(y0, y1, acc[1][pp]);
            UNPACK2(z0, z1, acc[2][pp]);
            UNPACK2(w0, w1, acc[3][pp]);
            *(float4*)&f_s[(2 * p)     * 1152 + fci * 36 + fco] = make_float4(x0, y0, z0, w0);
            *(float4*)&f_s[(2 * p + 1) * 1152 + fci * 36 + fco] = make_float4(x1, y1, z1, w1);
        }
        __syncthreads();

        // apply (f32x2): 2 batches x 8 co per thread, one edge
        if (es0 + ea < net) {
            const float* gp0 = &g_s[ea * 576 + b0 * 36];
            const float* gp1 = gp0 + 36;
            const unsigned fpa = smb + (OFF_F + ea * 1152 + j0) * 4;
            u64 a0[4] = {0ull, 0ull, 0ull, 0ull};
            u64 a1[4] = {0ull, 0ull, 0ull, 0ull};
            #pragma unroll
            for (int ci4 = 0; ci4 < 32; ci4 += 4) {
                float4 gv0 = *(const float4*)&gp0[ci4];
                float4 gv1 = *(const float4*)&gp1[ci4];
                float g0v[4] = {gv0.x, gv0.y, gv0.z, gv0.w};
                float g1v[4] = {gv1.x, gv1.y, gv1.z, gv1.w};
                #pragma unroll
                for (int kk = 0; kk < 4; kk++) {
                    u64 f01, f23, f45, f67;
                    LDS_V2B64(f01, f23, fpa + (ci4 + kk) * 144);
                    LDS_V2B64(f45, f67, fpa + (ci4 + kk) * 144 + 16);
                    u64 d0; PACK2(d0, g0v[kk], g0v[kk]);
                    FMA2(a0[0], d0, f01, a0[0]);
                    FMA2(a0[1], d0, f23, a0[1]);
                    FMA2(a0[2], d0, f45, a0[2]);
                    FMA2(a0[3], d0, f67, a0[3]);
                    u64 d1; PACK2(d1, g1v[kk], g1v[kk]);
                    FMA2(a1[0], d1, f01, a1[0]);
                    FMA2(a1[1], d1, f23, a1[1]);
                    FMA2(a1[2], d1, f45, a1[2]);
                    FMA2(a1[3], d1, f67, a1[3]);
                }
            }
            size_t m = (size_t)(e0 + es0 + ea) * 32 + j0;
            float* vb0 = &g_Vbuf[(size_t)b0 * VB_STRIDE + m];
            float* vb1 = vb0 + VB_STRIDE;
            ulonglong2 s0a; s0a.x = a0[0]; s0a.y = a0[1];
            ulonglong2 s0b; s0b.x = a0[2]; s0b.y = a0[3];
            ulonglong2 s1a; s1a.x = a1[0]; s1a.y = a1[1];
            ulonglong2 s1b; s1b.x = a1[2]; s1b.y = a1[3];
            *(ulonglong2*)vb0       = s0a;
            *(ulonglong2*)(vb0 + 4) = s0b;
            *(ulonglong2*)vb1       = s1a;
            *(ulonglong2*)(vb1 + 4) = s1b;
        }
        __syncthreads();
    }
}

// ---------------- phase B: out[b][c][o] = sum over seg-range of Vbuf[b][c*E + r]
__global__ __launch_bounds__(512) void quad_scatter(float* __restrict__ out, int E)
{
    const int o  = blockIdx.x;
    const int c0 = blockIdx.y * 4;
    const int r0 = g_bnd[o];
    const int r1 = g_bnd[o + 1];

    const int b = threadIdx.x >> 5;     // warp = batch
    const int l = threadIdx.x & 31;

    #pragma unroll
    for (int cc = 0; cc < 4; cc++) {
        int c = c0 + cc;
        const float* p = &g_Vbuf[(size_t)b * VB_STRIDE + (size_t)c * E];
        float s = 0.f;
        for (int r = r0 + l; r < r1; r += 32) s += p[r];
        #pragma unroll
        for (int d = 16; d; d >>= 1) s += __shfl_xor_sync(0xffffffffu, s, d);
        if (l == 0) out[b * 32768 + c * 1024 + o] = s;
    }
}

extern "C" void kernel_launch(void* const* d_in, const int* in_sizes, int n_in,
                              void* d_out, int out_size) {
    const float* features  = (const float*)d_in[0];
    const float* W1        = (const float*)d_in[1];
    const float* W2        = (const float*)d_in[2];
    const float* W3        = (const float*)d_in[3];
    const float* eval_locs = (const float*)d_in[4];
    const int*   eval_idx  = (const int*)d_in[5];
    float*       out       = (float*)d_out;

    const int E = in_sizes[4] / 2;

    cudaFuncSetAttribute(quad_main, cudaFuncAttributeMaxDynamicSharedMemorySize,
                         SMEM_A_BYTES);

    detect_idx<<<1, 256>>>(eval_idx, E);
    convert_idx<<<(E + 255) / 256, 256>>>(eval_idx, E);
    seg_bounds<<<(N_OUT + 256) / 256, 256>>>(E);
    prep_featT<<<dim3(N_IN / 32, 512 / 32), dim3(32, 8)>>>(features);
    quad_main<<<(E + 15) / 16, 256, SMEM_A_BYTES>>>(W1, W2, W3, eval_locs, E);
    quad_scatter<<<dim3(N_OUT, 8), 512>>>(out, E);
}

// round 11
// speedup vs baseline: 1.2765x; 1.1937x over previous
#include <cuda_runtime.h>
#include <math.h>

typedef unsigned long long u64;

#define FMA2(d, a, b, c) \
    asm("fma.rn.f32x2 %0, %1, %2, %3;" : "=l"(d) : "l"(a), "l"(b), "l"(c))
#define PACK2(d, lo, hi) \
    asm("mov.b64 %0, {%1, %2};" : "=l"(d) : "f"(lo), "f"(hi))
#define UNPACK2(lo, hi, d) \
    asm("mov.b64 {%0, %1}, %2;" : "=f"(lo), "=f"(hi) : "l"(d))
#define LDS_V2B64(a, b, addr) \
    asm volatile("ld.shared.v2.b64 {%0, %1}, [%2];" : "=l"(a), "=l"(b) : "r"(addr))

#define N_IN   4096
#define N_OUT  1024
#define BATCH  16
#define E_MAX  81920

__device__ float g_featT2[N_IN * 512];                 // [n][c*16+b]
__device__ int   g_is64;
__device__ int   g_seg[E_MAX];
__device__ int   g_src[E_MAX];

// ---------------- phase -1: dtype detect + index normalize ------------------
__global__ void detect_idx(const int* __restrict__ idx32, int E) {
    __shared__ int any;
    if (threadIdx.x == 0) any = 0;
    __syncthreads();
    int n = min(E, 512);
    int local = 0;
    for (int m = threadIdx.x; m < n; m += 256)
        local |= idx32[4 * m + 1] | idx32[4 * m + 3];
    if (local) atomicOr(&any, 1);
    __syncthreads();
    if (threadIdx.x == 0) g_is64 = any ? 0 : 1;
}

__global__ void convert_idx(const int* __restrict__ idx32, int E) {
    int m = blockIdx.x * 256 + threadIdx.x;
    if (m >= E) return;
    if (g_is64) { g_seg[m] = idx32[4 * m];     g_src[m] = idx32[4 * m + 2]; }
    else        { g_seg[m] = idx32[2 * m];     g_src[m] = idx32[2 * m + 1]; }
}

// ---------------- zero-init output (poisoned 0xAA; empty segments must be 0)
__global__ void zero_out(float* __restrict__ out) {
    out[blockIdx.x * 256 + threadIdx.x] = 0.f;
}

// ---------------- phase 0: tiled permute feat[b][c][n] -> featT2[n][c*16+b]
__global__ void prep_featT(const float* __restrict__ feat) {
    __shared__ float tile[32][33];
    int n0  = blockIdx.x * 32;
    int cb0 = blockIdx.y * 32;
    int tx = threadIdx.x, ty = threadIdx.y;       // 32 x 8
    #pragma unroll
    for (int i = ty; i < 32; i += 8) {
        int cb = cb0 + i;
        int row = (cb & 15) * 32 + (cb >> 4);     // b*32 + c
        tile[i][tx] = feat[(size_t)row * N_IN + n0 + tx];
    }
    __syncthreads();
    #pragma unroll
    for (int i = ty; i < 32; i += 8)
        g_featT2[(size_t)(n0 + i) * 512 + cb0 + tx] = tile[tx][i];
}

// ---------------- phase A (fused: MLP + filter + apply + segment reduce) ----
// 256 threads, 16 edges/block, 2 blocks/SM. smem (floats):
//  h1 [16][64]     @0      (1024)
//  h2t[64][20]     @1024   (1280)
//  W2s[64][64]     @2304   (4096)
//  g  [8][16][36]  @6400   (4608)   <- overlaid by vals[16][264] after apply
//  filt[8][32][36] @11008  (9216)
//  locs[32]        @20224
//  goff[512] int   @20256
//  keys[512] int   @20768
//  gstart[2][66]+ng[2] int @21280
#define OFF_H1   0
#define OFF_H2T  1024
#define OFF_W2S  2304
#define OFF_G    6400
#define OFF_F    11008
#define OFF_LOCS 20224
#define OFF_GOFF 20256
#define OFF_KEYS 20768
#define OFF_GST  21280
#define SMEM_A_FLOATS 21416
#define SMEM_A_BYTES  (SMEM_A_FLOATS * 4)
#define VROW 264

__global__ __launch_bounds__(256, 2) void quad_main(
    const float* __restrict__ W1, const float* __restrict__ W2,
    const float* __restrict__ W3, const float* __restrict__ eval_locs,
    float* __restrict__ out, int E)
{
    extern __shared__ float sm[];
    float* h1_s   = sm + OFF_H1;
    float* h2t    = sm + OFF_H2T;
    float* W2s    = sm + OFF_W2S;
    float* g_s    = sm + OFF_G;
    float* vals_s = sm + OFF_G;        // overlay after apply
    float* f_s    = sm + OFF_F;
    float* locs   = sm + OFF_LOCS;
    int*   goff   = (int*)(sm + OFF_GOFF);
    int*   keys_s = (int*)(sm + OFF_KEYS);
    int*   gst    = (int*)(sm + OFF_GST);       // [2][66]
    int*   ng_s   = (int*)(sm + OFF_GST) + 132; // [2]
    const unsigned smb = (unsigned)__cvta_generic_to_shared(sm);

    const int t   = threadIdx.x;
    const int e0  = blockIdx.x * 16;
    const int net = min(16, E - e0);
    const int mb  = blockIdx.x * 512;   // flat vals base for this block

    if (t < 2 * net) locs[t] = eval_locs[2 * e0 + t];

    // stage W2 into smem (coalesced, once per block)
    #pragma unroll
    for (int r = 0; r < 16; r++)
        W2s[t + 256 * r] = W2[t + 256 * r];

    // gather offsets per (e, ci) AND scramble keys per flat pos p
    #pragma unroll
    for (int r = 0; r < 2; r++) {
        int p = t + 256 * r;              // 0..511
        int key = -1;
        if (p < net * 32) {
            int m  = mb + p;
            int c  = m / E;
            int rr = m - c * E;
            goff[p] = g_src[rr] * 512 + c * 16;
            key = (c << 10) + g_seg[rr];
        }
        keys_s[p] = key;
    }
    __syncthreads();

    // warps 0/1: run-boundary scan of keys for sub 0/1
    if (t < 64) {
        int sub  = t >> 5, l = t & 31;
        int base = sub * 256;
        int cnt = 0, st[8];
        #pragma unroll
        for (int i = 0; i < 8; i++) {
            int p = base + l * 8 + i;
            int kprev = (p == base) ? 0x7fffffff : keys_s[p - 1];
            if (keys_s[p] != kprev) st[cnt++] = p;
        }
        unsigned off = (unsigned)cnt;
        #pragma unroll
        for (int d = 1; d < 32; d <<= 1) {
            unsigned v = __shfl_up_sync(0xffffffffu, off, d);
            if (l >= d) off += v;
        }
        int excl = (int)off - cnt;
        for (int i = 0; i < cnt; i++) gst[sub * 66 + excl + i] = st[i];
        if (l == 31) { ng_s[sub] = (int)off; gst[sub * 66 + (int)off] = base + 256; }
    }

    // h1[e][j] = sin(loc_e . W1[:,j])   (0 for padded edges)
    #pragma unroll
    for (int r = 0; r < 4; r++) {
        int id = t + 256 * r;             // 0..1023
        int e = id >> 6, j = id & 63;
        float v = 0.f;
        if (e < net)
            v = __sinf(locs[2 * e] * W1[j] + locs[2 * e + 1] * W1[64 + j]);
        h1_s[id] = v;
    }
    __syncthreads();

    // ---- h2 (f32x2): thread owns (e = t>>4, cols j0..j0+3); writes h2t[j][e]
    {
        const int e  = t >> 4;
        const int j0 = (t & 15) * 4;
        u64 aA = 0ull, aB = 0ull;
        #pragma unroll
        for (int k4 = 0; k4 < 64; k4 += 4) {
            float4 hv = *(const float4*)&h1_s[e * 64 + k4];
            float hs[4] = {hv.x, hv.y, hv.z, hv.w};
            #pragma unroll
            for (int kk = 0; kk < 4; kk++) {
                u64 hh; PACK2(hh, hs[kk], hs[kk]);
                u64 w01, w23;
                LDS_V2B64(w01, w23, smb + (OFF_W2S + (k4 + kk) * 64 + j0) * 4);
                FMA2(aA, hh, w01, aA);
                FMA2(aB, hh, w23, aB);
            }
        }
        float s0, s1, s2, s3;
        UNPACK2(s0, s1, aA);
        UNPACK2(s2, s3, aB);
        s0 = __sinf(s0); s1 = __sinf(s1); s2 = __sinf(s2); s3 = __sinf(s3);
        if (e >= net) { s0 = s1 = s2 = s3 = 0.f; }
        h2t[(j0 + 0) * 20 + e] = s0;
        h2t[(j0 + 1) * 20 + e] = s1;
        h2t[(j0 + 2) * 20 + e] = s2;
        h2t[(j0 + 3) * 20 + e] = s3;
    }
    __syncthreads();

    // ---- filter gen (f32x2): thread owns 4 cols {4t..4t+3}, all 16 edges.
    u64 acc[4][8];
    #pragma unroll
    for (int c = 0; c < 4; c++)
        #pragma unroll
        for (int p = 0; p < 8; p++) acc[c][p] = 0ull;

    const float4* w3p4 = (const float4*)W3 + t;     // row stride 256 float4
    float4 wcur = w3p4[0];

    #pragma unroll 8
    for (int k = 0; k < 64; k++) {
        float4 wnext = (k < 63) ? w3p4[(k + 1) * 256] : wcur;
        u64 wa, wb, wc, wd;
        PACK2(wa, wcur.x, wcur.x);
        PACK2(wb, wcur.y, wcur.y);
        PACK2(wc, wcur.z, wcur.z);
        PACK2(wd, wcur.w, wcur.w);
        const unsigned ha = smb + (OFF_H2T + k * 20) * 4;
        u64 hp[8];
        LDS_V2B64(hp[0], hp[1], ha);
        LDS_V2B64(hp[2], hp[3], ha + 16);
        LDS_V2B64(hp[4], hp[5], ha + 32);
        LDS_V2B64(hp[6], hp[7], ha + 48);
        #pragma unroll
        for (int p = 0; p < 8; p++) {
            FMA2(acc[0][p], wa, hp[p], acc[0][p]);
            FMA2(acc[1][p], wb, hp[p], acc[1][p]);
            FMA2(acc[2][p], wc, hp[p], acc[2][p]);
            FMA2(acc[3][p], wd, hp[p], acc[3][p]);
        }
        wcur = wnext;
    }

    // mappings
    const int fci = t >> 3;              // filt store: col 4t -> ci
    const int fco = (t & 7) * 4;
    const int ea  = t >> 5;              // apply: edge within sub (0..7)
    const int b0  = ((t >> 2) & 7) * 2;  //        2 batches
    const int j0  = (t & 3) * 8;         //        8 consecutive co

    #pragma unroll
    for (int sub = 0; sub < 2; sub++) {
        const int es0 = sub * 8;

        // staged gather of 8 edges: g[e][b][ci]
        #pragma unroll
        for (int r = 0; r < 16; r++) {
            int i  = t + 256 * r;             // 0..4095
            int p8 = i >> 4;                  // (e,ci) 0..255
            int b  = i & 15;
            int e  = p8 >> 5, ci = p8 & 31;
            float v = (es0 + e < net) ? g_featT2[goff[(es0 + e) * 32 + ci] + b] : 0.f;
            g_s[e * 576 + b * 36 + ci] = v;
        }
        // store this sub's filters: edge pairs 4*sub..4*sub+3
        #pragma unroll
        for (int p = 0; p < 4; p++) {
            int pp = sub * 4 + p;
            float x0, x1, y0, y1, z0, z1, w0, w1;
            UNPACK2(x0, x1, acc[0][pp]);
            UNPACK2(y0, y1, acc[1][pp]);
            UNPACK2(z0, z1, acc[2][pp]);
            UNPACK2(w0, w1, acc[3][pp]);
            *(float4*)&f_s[(2 * p)     * 1152 + fci * 36 + fco] = make_float4(x0, y0, z0, w0);
            *(float4*)&f_s[(2 * p + 1) * 1152 + fci * 36 + fco] = make_float4(x1, y1, z1, w1);
        }
        __syncthreads();

        // apply (f32x2): 2 batches x 8 co per thread, one edge
        u64 a0[4] = {0ull, 0ull, 0ull, 0ull};
        u64 a1[4] = {0ull, 0ull, 0ull, 0ull};
        if (es0 + ea < net) {
            const float* gp0 = &g_s[ea * 576 + b0 * 36];
            const float* gp1 = gp0 + 36;
            const unsigned fpa = smb + (OFF_F + ea * 1152 + j0) * 4;
            #pragma unroll
            for (int ci4 = 0; ci4 < 32; ci4 += 4) {
                float4 gv0 = *(const float4*)&gp0[ci4];
                float4 gv1 = *(const float4*)&gp1[ci4];
                float g0v[4] = {gv0.x, gv0.y, gv0.z, gv0.w};
                float g1v[4] = {gv1.x, gv1.y, gv1.z, gv1.w};
                #pragma unroll
                for (int kk = 0; kk < 4; kk++) {
                    u64 f01, f23, f45, f67;
                    LDS_V2B64(f01, f23, fpa + (ci4 + kk) * 144);
                    LDS_V2B64(f45, f67, fpa + (ci4 + kk) * 144 + 16);
                    u64 d0; PACK2(d0, g0v[kk], g0v[kk]);
                    FMA2(a0[0], d0, f01, a0[0]);
                    FMA2(a0[1], d0, f23, a0[1]);
                    FMA2(a0[2], d0, f45, a0[2]);
                    FMA2(a0[3], d0, f67, a0[3]);
                    u64 d1; PACK2(d1, g1v[kk], g1v[kk]);
                    FMA2(a1[0], d1, f01, a1[0]);
                    FMA2(a1[1], d1, f23, a1[1]);
                    FMA2(a1[2], d1, f45, a1[2]);
                    FMA2(a1[3], d1, f67, a1[3]);
                }
            }
        }
        __syncthreads();   // all reads of g_s / f_s complete

        // dump vals to smem (overlay g_s): vals[b][ea*32 + j0 .. +7]
        {
            float* vp0 = &vals_s[b0 * VROW + ea * 32 + j0];
            float* vp1 = vp0 + VROW;
            ulonglong2 s0a; s0a.x = a0[0]; s0a.y = a0[1];
            ulonglong2 s0b; s0b.x = a0[2]; s0b.y = a0[3];
            ulonglong2 s1a; s1a.x = a1[0]; s1a.y = a1[1];
            ulonglong2 s1b; s1b.x = a1[2]; s1b.y = a1[3];
            *(ulonglong2*)vp0       = s0a;
            *(ulonglong2*)(vp0 + 4) = s0b;
            *(ulonglong2*)vp1       = s1a;
            *(ulonglong2*)(vp1 + 4) = s1b;
        }
        __syncthreads();   // vals ready

        // segment reduce: one (b, group) per task -> single atomicAdd
        {
            const int ng = ng_s[sub];
            const int base = sub * 256;
            for (int task = t; task < 16 * ng; task += 256) {
                int b  = task / ng;
                int gi = task - b * ng;
                int p0 = gst[sub * 66 + gi];
                int p1 = gst[sub * 66 + gi + 1];
                int key = keys_s[p0];
                if (key >= 0) {
                    const float* vp = &vals_s[b * VROW - base];
                    float s = 0.f;
                    for (int p = p0; p < p1; p++) s += vp[p];
                    atomicAdd(&out[(size_t)b * 32768 + key], s);
                }
            }
        }
        __syncthreads();   // before next sub overwrites vals/g_s
    }
}

extern "C" void kernel_launch(void* const* d_in, const int* in_sizes, int n_in,
                              void* d_out, int out_size) {
    const float* features  = (const float*)d_in[0];
    const float* W1        = (const float*)d_in[1];
    const float* W2        = (const float*)d_in[2];
    const float* W3        = (const float*)d_in[3];
    const float* eval_locs = (const float*)d_in[4];
    const int*   eval_idx  = (const int*)d_in[5];
    float*       out       = (float*)d_out;

    const int E = in_sizes[4] / 2;

    cudaFuncSetAttribute(quad_main, cudaFuncAttributeMaxDynamicSharedMemorySize,
                         SMEM_A_BYTES);

    detect_idx<<<1, 256>>>(eval_idx, E);
    convert_idx<<<(E + 255) / 256, 256>>>(eval_idx, E);
    prep_featT<<<dim3(N_IN / 32, 512 / 32), dim3(32, 8)>>>(features);
    zero_out<<<(BATCH * 32 * N_OUT) / 256, 256>>>(out);
    quad_main<<<(E + 15) / 16, 256, SMEM_A_BYTES>>>(
        W1, W2, W3, eval_locs, out, E);
}